// round 13
// baseline (speedup 1.0000x reference)
#include <cuda_runtime.h>
#include <cuda_bf16.h>
#include <stdint.h>

#define BATCH 4
#define CDIM  256
#define HH    120
#define WWID  120
#define SP    (HH*WWID)
#define NB    24
#define NWIN  (BATCH*NB*NB)       // 2304
#define NPOS  (BATCH*SP)          // 57600
#define QSCALE 0.17677669529663688f

#define NEGW  (-0.5f)
#define POSW  (4.0f/3.0f)
#define NORW  (-0.375f)
#define CNORW (4.0f)
#define PW    (1.8333333333333333f)   // POSW - NEGW
#define C0W   (4.375f)                // CNORW - NORW

// fp32 projections (read by attn)
__device__ float g_xk[NPOS*CDIM];
__device__ float g_xv[NPOS*CDIM];
__device__ float g_xq[NPOS*CDIM];
// bf16 split inputs for MMA
__device__ __nv_bfloat16 g_xh[NPOS*CDIM];
__device__ __nv_bfloat16 g_xl[NPOS*CDIM];
__device__ __nv_bfloat16 g_yh[NPOS*CDIM];
__device__ __nv_bfloat16 g_yl[NPOS*CDIM];
__device__ __nv_bfloat16 g_wh[4*CDIM*CDIM];   // Wk,Wv,Wq,Wout
__device__ __nv_bfloat16 g_wl[4*CDIM*CDIM];

__device__ __forceinline__ uint32_t sptr(const void* p) {
    return (uint32_t)__cvta_generic_to_shared(p);
}

#define LDM_X4(R, A) asm volatile( \
    "ldmatrix.sync.aligned.m8n8.x4.shared.b16 {%0,%1,%2,%3}, [%4];" \
    : "=r"((R)[0]), "=r"((R)[1]), "=r"((R)[2]), "=r"((R)[3]) : "r"(A))

#define MMA_BF16(D, A, B0, B1) asm volatile( \
    "mma.sync.aligned.m16n8k16.row.col.f32.bf16.bf16.f32 " \
    "{%0,%1,%2,%3},{%4,%5,%6,%7},{%8,%9},{%0,%1,%2,%3};" \
    : "+f"((D)[0]), "+f"((D)[1]), "+f"((D)[2]), "+f"((D)[3]) \
    : "r"((A)[0]), "r"((A)[1]), "r"((A)[2]), "r"((A)[3]), "r"(B0), "r"(B1))

#define CP_ASYNC16(dst, src) asm volatile( \
    "cp.async.cg.shared.global [%0], [%1], 16;" :: "r"(dst), "l"(src))
#define CP_COMMIT() asm volatile("cp.async.commit_group;")
#define CP_WAIT1()  asm volatile("cp.async.wait_group 1;")
#define CP_WAIT0()  asm volatile("cp.async.wait_group 0;")

// ---- packed f32x2 (Blackwell sm_100+) ----
#define FMA2(d, a, b) asm("fma.rn.f32x2 %0, %1, %2, %0;" : "+l"(d) : "l"(a), "l"(b))
#define ADD2(d, a, b) asm("add.rn.f32x2 %0, %1, %2;" : "=l"(d) : "l"(a), "l"(b))
#define PACK2(d, s)   asm("mov.b64 %0, {%1, %1};" : "=l"(d) : "r"(s))
#define UNPACK2(lo, hi, v) asm("mov.b64 {%0, %1}, %2;" : "=r"(lo), "=r"(hi) : "l"(v))

// ---------------------------------------------------------------------------
// Convert x [b][k][p] fp32 -> g_xh/g_xl [b*SP + p][k] bf16 hi/lo (transpose)
// ---------------------------------------------------------------------------
__global__ __launch_bounds__(256) void convertX_kernel(const float* __restrict__ x)
{
    __shared__ float st[64][65];
    const int p0 = blockIdx.x * 64;
    const int k0 = blockIdx.y * 64;
    const int b  = blockIdx.z;
    const int t  = threadIdx.x;

    for (int idx = t; idx < 4096; idx += 256) {
        const int k = idx >> 6, p = idx & 63;
        st[k][p] = x[((size_t)b * CDIM + k0 + k) * SP + p0 + p];
    }
    __syncthreads();
    for (int idx = t; idx < 2048; idx += 256) {
        const int p = idx >> 5, kk = idx & 31, k = kk * 2;
        const float v0 = st[k][p], v1 = st[k + 1][p];
        const __nv_bfloat16 h0 = __float2bfloat16(v0);
        const __nv_bfloat16 h1 = __float2bfloat16(v1);
        const __nv_bfloat16 l0 = __float2bfloat16(v0 - __bfloat162float(h0));
        const __nv_bfloat16 l1 = __float2bfloat16(v1 - __bfloat162float(h1));
        const size_t o = ((size_t)b * SP + p0 + p) * CDIM + k0 + k;
        *(__nv_bfloat162*)&g_xh[o] = __halves2bfloat162(h0, h1);
        *(__nv_bfloat162*)&g_xl[o] = __halves2bfloat162(l0, l1);
    }
}

__global__ __launch_bounds__(256) void convertW_kernel(
    const float* __restrict__ Wk, const float* __restrict__ Wv,
    const float* __restrict__ Wq, const float* __restrict__ Wout)
{
    const int i = blockIdx.x * 256 + threadIdx.x;   // 0..65535
    const float* srcs[4] = {Wk, Wv, Wq, Wout};
#pragma unroll
    for (int m = 0; m < 4; m++) {
        const float v = srcs[m][i];
        const __nv_bfloat16 h = __float2bfloat16(v);
        g_wh[m * 65536 + i] = h;
        g_wl[m * 65536 + i] = __float2bfloat16(v - __bfloat162float(h));
    }
}

// ---------------------------------------------------------------------------
// proj3 via mma.sync, cp.async double-buffered.  KC=32, 8 chunks.
// ---------------------------------------------------------------------------
#define PJ_STAGE 51200
#define PJ_SMEM  (2*PJ_STAGE)      // 102400

__device__ __forceinline__ void pj_load_chunk(char* base, int t, int row0, int c0,
                                              int chunk)
{
    const int kc = chunk * 32;
    for (int i = t; i < 1024; i += 256) {
        const int half = i >> 9, r = (i >> 2) & 127, seg = i & 3;
        const __nv_bfloat16* src = (half ? g_xl : g_xh)
            + (size_t)(row0 + r) * CDIM + kc + seg * 8;
        CP_ASYNC16(sptr(base + half * 10240 + r * 80 + seg * 16), src);
    }
    for (int i = t; i < 1536; i += 256) {
        const int half = (i >= 768), rem = i - half * 768;
        const int pr = rem >> 8, rr = (rem >> 2) & 63, seg = rem & 3;
        const __nv_bfloat16* src = (half ? g_wl : g_wh)
            + (size_t)pr * 65536 + (size_t)(c0 + rr) * CDIM + kc + seg * 8;
        CP_ASYNC16(sptr(base + 20480 + half * 15360 + pr * 5120 + rr * 80 + seg * 16),
                   src);
    }
}

__global__ __launch_bounds__(256, 2) void proj_mma_kernel()
{
    extern __shared__ char smem[];
    const int t = threadIdx.x;
    const int warp = t >> 5, lane = t & 31;
    const int wm = warp >> 1, wn = warp & 1;
    const int row0 = blockIdx.x * 128;
    const int c0   = blockIdx.y * 64;

    float acc[3][2][4][4];
#pragma unroll
    for (int a = 0; a < 3; a++)
#pragma unroll
        for (int b = 0; b < 2; b++)
#pragma unroll
            for (int c = 0; c < 4; c++)
#pragma unroll
                for (int d = 0; d < 4; d++) acc[a][b][c][d] = 0.f;

    pj_load_chunk(smem, t, row0, c0, 0);
    CP_COMMIT();

    for (int ch = 0; ch < 8; ch++) {
        if (ch < 7) {
            pj_load_chunk(smem + ((ch + 1) & 1) * PJ_STAGE, t, row0, c0, ch + 1);
            CP_COMMIT();
            CP_WAIT1();
        } else {
            CP_WAIT0();
        }
        __syncthreads();
        char* base = smem + (ch & 1) * PJ_STAGE;

#pragma unroll
        for (int ks = 0; ks < 2; ks++) {
            uint32_t Ah[2][4], Al[2][4];
            const int colb = ks * 32 + ((lane >> 4) << 4);
#pragma unroll
            for (int mt = 0; mt < 2; mt++) {
                const int r = wm * 32 + mt * 16 + (lane & 15);
                LDM_X4(Ah[mt], sptr(base + r * 80 + colb));
                LDM_X4(Al[mt], sptr(base + 10240 + r * 80 + colb));
            }
#pragma unroll
            for (int pr = 0; pr < 3; pr++) {
#pragma unroll
                for (int pair = 0; pair < 2; pair++) {
                    const int nr = wn * 32 + pair * 16 + (lane & 15);
                    uint32_t bh[4], bl[4];
                    LDM_X4(bh, sptr(base + 20480 + pr * 5120 + nr * 80 + colb));
                    LDM_X4(bl, sptr(base + 35840 + pr * 5120 + nr * 80 + colb));
#pragma unroll
                    for (int mt = 0; mt < 2; mt++) {
#pragma unroll
                        for (int sub = 0; sub < 2; sub++) {
                            const int nt = pair * 2 + sub;
                            MMA_BF16(acc[pr][mt][nt], Ah[mt], bh[sub], bh[sub + 2]);
                            MMA_BF16(acc[pr][mt][nt], Ah[mt], bl[sub], bl[sub + 2]);
                            MMA_BF16(acc[pr][mt][nt], Al[mt], bh[sub], bh[sub + 2]);
                        }
                    }
                }
            }
        }
        __syncthreads();
    }

    const int rbase = row0 + wm * 32 + (lane >> 2);
    const int cbase = c0 + wn * 32 + (lane & 3) * 2;
    float* dsts[3] = {g_xk, g_xv, g_xq};
#pragma unroll
    for (int pr = 0; pr < 3; pr++) {
        const float s = (pr == 2) ? QSCALE : 1.f;
#pragma unroll
        for (int mt = 0; mt < 2; mt++) {
#pragma unroll
            for (int nt = 0; nt < 4; nt++) {
                const int r = rbase + mt * 16;
                const int c = cbase + nt * 8;
                float* d = dsts[pr];
                *(float2*)&d[(size_t)r * CDIM + c] =
                    make_float2(acc[pr][mt][nt][0] * s, acc[pr][mt][nt][1] * s);
                *(float2*)&d[(size_t)(r + 8) * CDIM + c] =
                    make_float2(acc[pr][mt][nt][2] * s, acc[pr][mt][nt][3] * s);
            }
        }
    }
}

// ---------------------------------------------------------------------------
// attn: CTA = (window, head-half). 128 threads = 4 warps = 4 heads, lane = q.
// Two-stage staging: K patch -> phase 1 (S into compact sS) -> barrier ->
// V patch overwrites the SAME buffer -> phase 2 (A window + fused AV).
// smem = 25088 (KV) + 19600 (S, stride 25, conflict-free) = 44688 B
// -> 5 CTAs/SM (20 warps) instead of 4.
// ---------------------------------------------------------------------------
#define ATTN_SMEM_BYTES ((4*49*32 + 4*49*25) * 4)   // 44688
__global__ __launch_bounds__(128, 5) void attn_kernel()
{
    extern __shared__ float sm_att[];
    float* sKV = sm_att;                  // 6272 floats: K, then V
    float* sS  = sm_att + 4 * 49 * 32;    // 4900 floats: [warp][p][lane<25]

    const int blk  = blockIdx.x;
    const int half = blockIdx.y;
    const int b    = blk / (NB * NB);
    const int wrem = blk % (NB * NB);
    const int wy = wrem / NB, wx = wrem % NB;
    const int t = threadIdx.x;
    const int c0 = half * 128;
    const int lane = t & 31;
    const int hl   = t >> 5;          // warp = head within this half

    const int ky0 = wy * 5 - 1, kx0 = wx * 5 - 1;

    // ---- stage K ----
    for (int idx = t; idx < 49 * 32; idx += 128) {
        const int r  = idx >> 5;
        const int c4 = idx & 31;
        const int y  = ky0 + r / 7;
        const int xx = kx0 + r % 7;
        float4 vk = make_float4(0.f, 0.f, 0.f, 0.f);
        if (y >= 0 && y < HH && xx >= 0 && xx < WWID) {
            vk = *(const float4*)&g_xk[((size_t)b * SP + y * WWID + xx) * CDIM
                                       + c0 + c4 * 4];
        }
        const int f = c4 * 4;
        *(float4*)&sKV[((f >> 5) * 49 + r) * 32 + (f & 31)] = vk;
    }
    __syncthreads();

    const int q = lane;
    const int qy = q / 5, qx = q % 5;
    const size_t qpos = ((size_t)b * SP + (wy * 5 + qy) * WWID + wx * 5 + qx) * CDIM
                        + (half * 4 + hl) * 32;
    float* Ss = &sS[hl * 49 * 25 + lane];     // stride 25 floats per p
    float m = 0.f;

    // ---- phase 1: S = Q . K ----
    if (lane < 25) {
        unsigned long long qp[16];
#pragma unroll
        for (int j = 0; j < 8; j++) {
            const ulonglong2 v = *(const ulonglong2*)&g_xq[qpos + j * 4];
            qp[2*j] = v.x; qp[2*j+1] = v.y;
        }
        float mpos = -3.4e38f, mneg = 3.4e38f;
#pragma unroll
        for (int p = 0; p < 49; p++) {
            const float* kr = &sKV[(hl * 49 + p) * 32];
            unsigned long long a0 = 0ull, a1 = 0ull;
#pragma unroll
            for (int j = 0; j < 8; j++) {
                const ulonglong2 kv = *(const ulonglong2*)&kr[j * 4];
                FMA2(a0, qp[2*j],   kv.x);
                FMA2(a1, qp[2*j+1], kv.y);
            }
            unsigned long long asum; ADD2(asum, a0, a1);
            uint32_t lo, hi; UNPACK2(lo, hi, asum);
            const float sv = __uint_as_float(lo) + __uint_as_float(hi);
            mpos = fmaxf(mpos, sv);
            mneg = fminf(mneg, sv);
            Ss[p * 25] = sv;
        }
        m = 4.0f * mpos - 3.0f * mneg;
    }
    __syncthreads();    // all warps done with K + S writes

    // ---- stage V (overwrites K buffer) ----
    for (int idx = t; idx < 49 * 32; idx += 128) {
        const int r  = idx >> 5;
        const int c4 = idx & 31;
        const int y  = ky0 + r / 7;
        const int xx = kx0 + r % 7;
        float4 vv = make_float4(0.f, 0.f, 0.f, 0.f);
        if (y >= 0 && y < HH && xx >= 0 && xx < WWID) {
            vv = *(const float4*)&g_xv[((size_t)b * SP + y * WWID + xx) * CDIM
                                       + c0 + c4 * 4];
        }
        const int f = c4 * 4;
        *(float4*)&sKV[((f >> 5) * 49 + r) * 32 + (f & 31)] = vv;
    }
    __syncthreads();

    // ---- phase 2: logits/softmax window + fused AV ----
    if (lane < 25) {
        unsigned long long o2[16];
#pragma unroll
        for (int j = 0; j < 16; j++) o2[j] = 0ull;
        float A0[7], A1[7], A2[7];
#pragma unroll
        for (int j = 0; j < 7; j++) { A0[j] = 0.f; A1[j] = 0.f; A2[j] = 0.f; }

        float ssum = 0.f;
#pragma unroll
        for (int ky = 0; ky < 5; ky++) {
            float a0 = Ss[(ky*7)*25],     a1 = Ss[((ky+1)*7)*25],     a2 = Ss[((ky+2)*7)*25];
            float b0 = Ss[(ky*7 + 1)*25], b1 = Ss[((ky+1)*7 + 1)*25], b2 = Ss[((ky+2)*7 + 1)*25];
#pragma unroll
            for (int kx = 0; kx < 5; kx++) {
                const float t0 = Ss[(ky*7 + kx + 2)*25];
                const float t1 = Ss[((ky+1)*7 + kx + 2)*25];
                const float t2 = Ss[((ky+2)*7 + kx + 2)*25];
                const float tl = a0, l = a1, bl = a2;
                const float u  = b0, c = b1, d  = b2;
                const float tr = t0, r = t1, br = t2;
                const float s_ud = u + d, s_lr = l + r;
                const float dg = tl + br, ad = tr + bl;
                const float sum9 = ((s_ud + s_lr) + (dg + ad)) + c;
                const float base = fmaf(NEGW, sum9, -m);
                const float e0 = __expf(fmaf(NORW, sum9, fmaf(C0W, c, -m)));
                const float e1 = __expf(fmaf(PW, s_ud + c, base));
                const float e2 = __expf(fmaf(PW, s_lr + c, base));
                const float e3 = __expf(fmaf(PW, dg + c, base));
                const float e4 = __expf(fmaf(PW, ad + c, base));
                const float e5 = __expf(fmaf(PW, (u + l) + c, base));
                const float e6 = __expf(fmaf(PW, (u + r) + c, base));
                const float e7 = __expf(fmaf(PW, (l + d) + c, base));
                const float e8 = __expf(fmaf(PW, (r + d) + c, base));
                const float E = ((e1 + e2) + (e3 + e4)) + ((e5 + e6) + (e7 + e8));
                ssum += E + e0;
                const float basea = fmaf(NEGW, E, NORW * e0);
                A0[kx  ] += fmaf(PW, e3, basea);
                A0[kx+1] += fmaf(PW, (e1 + e5) + e6, basea);
                A0[kx+2] += fmaf(PW, e4, basea);
                A1[kx  ] += fmaf(PW, (e2 + e5) + e7, basea);
                A1[kx+1] += fmaf(PW, E, fmaf(C0W, e0, basea));
                A1[kx+2] += fmaf(PW, (e2 + e6) + e8, basea);
                A2[kx  ] += fmaf(PW, e4, basea);
                A2[kx+1] += fmaf(PW, (e1 + e7) + e8, basea);
                A2[kx+2] += fmaf(PW, e3, basea);
                a0 = b0; a1 = b1; a2 = b2;
                b0 = t0; b1 = t1; b2 = t2;
            }
            // row ky final: fused AV (V broadcasts)
#pragma unroll
            for (int px = 0; px < 7; px++) {
                unsigned long long aa; PACK2(aa, __float_as_uint(A0[px]));
                const float* vr = &sKV[(hl * 49 + ky * 7 + px) * 32];
#pragma unroll
                for (int j = 0; j < 8; j++) {
                    const ulonglong2 vv = *(const ulonglong2*)&vr[j * 4];
                    FMA2(o2[2*j],   aa, vv.x);
                    FMA2(o2[2*j+1], aa, vv.y);
                }
            }
#pragma unroll
            for (int j = 0; j < 7; j++) { A0[j] = A1[j]; A1[j] = A2[j]; A2[j] = 0.f; }
        }
        // rows 5 (A0) and 6 (A1)
#pragma unroll
        for (int rr = 0; rr < 2; rr++) {
#pragma unroll
            for (int px = 0; px < 7; px++) {
                const float a = rr ? A1[px] : A0[px];
                unsigned long long aa; PACK2(aa, __float_as_uint(a));
                const float* vr = &sKV[(hl * 49 + (5 + rr) * 7 + px) * 32];
#pragma unroll
                for (int j = 0; j < 8; j++) {
                    const ulonglong2 vv = *(const ulonglong2*)&vr[j * 4];
                    FMA2(o2[2*j],   aa, vv.x);
                    FMA2(o2[2*j+1], aa, vv.y);
                }
            }
        }

        const float inv = 1.0f / ssum;
#pragma unroll
        for (int g = 0; g < 4; g++) {
            uint32_t hw[4], lw[4];
#pragma unroll
            for (int jj = 0; jj < 4; jj++) {
                uint32_t lo, hi; UNPACK2(lo, hi, o2[g * 4 + jj]);
                const float v0 = __uint_as_float(lo) * inv;
                const float v1 = __uint_as_float(hi) * inv;
                const __nv_bfloat16 h0 = __float2bfloat16(v0);
                const __nv_bfloat16 h1 = __float2bfloat16(v1);
                const __nv_bfloat16 l0 = __float2bfloat16(v0 - __bfloat162float(h0));
                const __nv_bfloat16 l1 = __float2bfloat16(v1 - __bfloat162float(h1));
                __nv_bfloat162 hp = __halves2bfloat162(h0, h1);
                __nv_bfloat162 lp = __halves2bfloat162(l0, l1);
                hw[jj] = *(uint32_t*)&hp;
                lw[jj] = *(uint32_t*)&lp;
            }
            *(uint4*)&g_yh[qpos + g * 8] = make_uint4(hw[0], hw[1], hw[2], hw[3]);
            *(uint4*)&g_yl[qpos + g * 8] = make_uint4(lw[0], lw[1], lw[2], lw[3]);
        }
    }
}

// ---------------------------------------------------------------------------
// outproj via mma.sync, cp.async double-buffered.  KC=32, 8 chunks.
// ---------------------------------------------------------------------------
#define OP_STAGE 30720
#define OP_BIAS  (2*OP_STAGE)              // 61440, 256B bias
#define OP_SMEM  (2*OP_STAGE + 256)

__device__ __forceinline__ void op_load_chunk(char* base, int t, int row0, int c0,
                                              int chunk)
{
    const int kc = chunk * 32;
    for (int i = t; i < 1024; i += 256) {
        const int half = i >> 9, r = (i >> 2) & 127, seg = i & 3;
        const __nv_bfloat16* src = (half ? g_yl : g_yh)
            + (size_t)(row0 + r) * CDIM + kc + seg * 8;
        CP_ASYNC16(sptr(base + half * 10240 + r * 80 + seg * 16), src);
    }
    for (int i = t; i < 512; i += 256) {
        const int half = i >> 8, rr = (i >> 2) & 63, seg = i & 3;
        const __nv_bfloat16* src = (half ? g_wl : g_wh)
            + (size_t)3 * 65536 + (size_t)(c0 + rr) * CDIM + kc + seg * 8;
        CP_ASYNC16(sptr(base + 20480 + half * 5120 + rr * 80 + seg * 16), src);
    }
}

__global__ __launch_bounds__(256, 2) void outproj_mma_kernel(
    const float* __restrict__ bout, float* __restrict__ out)
{
    extern __shared__ char smem[];
    float* sT = (float*)smem;
    float* sBias = (float*)(smem + OP_BIAS);
    const int t = threadIdx.x;
    const int warp = t >> 5, lane = t & 31;
    const int wm = warp >> 1, wn = warp & 1;
    const int row0 = blockIdx.x * 128;
    const int c0   = blockIdx.y * 64;

    if (t < 64) sBias[t] = bout[c0 + t];

    float acc[2][4][4];
#pragma unroll
    for (int b = 0; b < 2; b++)
#pragma unroll
        for (int c = 0; c < 4; c++)
#pragma unroll
            for (int d = 0; d < 4; d++) acc[b][c][d] = 0.f;

    op_load_chunk(smem, t, row0, c0, 0);
    CP_COMMIT();

    for (int ch = 0; ch < 8; ch++) {
        if (ch < 7) {
            op_load_chunk(smem + ((ch + 1) & 1) * OP_STAGE, t, row0, c0, ch + 1);
            CP_COMMIT();
            CP_WAIT1();
        } else {
            CP_WAIT0();
        }
        __syncthreads();
        char* base = smem + (ch & 1) * OP_STAGE;

#pragma unroll
        for (int ks = 0; ks < 2; ks++) {
            uint32_t Ah[2][4], Al[2][4];
            const int colb = ks * 32 + ((lane >> 4) << 4);
#pragma unroll
            for (int mt = 0; mt < 2; mt++) {
                const int r = wm * 32 + mt * 16 + (lane & 15);
                LDM_X4(Ah[mt], sptr(base + r * 80 + colb));
                LDM_X4(Al[mt], sptr(base + 10240 + r * 80 + colb));
            }
#pragma unroll
            for (int pair = 0; pair < 2; pair++) {
                const int nr = wn * 32 + pair * 16 + (lane & 15);
                uint32_t bh[4], bl[4];
                LDM_X4(bh, sptr(base + 20480 + nr * 80 + colb));
                LDM_X4(bl, sptr(base + 25600 + nr * 80 + colb));
#pragma unroll
                for (int mt = 0; mt < 2; mt++) {
#pragma unroll
                    for (int sub = 0; sub < 2; sub++) {
                        const int nt = pair * 2 + sub;
                        MMA_BF16(acc[mt][nt], Ah[mt], bh[sub], bh[sub + 2]);
                        MMA_BF16(acc[mt][nt], Ah[mt], bl[sub], bl[sub + 2]);
                        MMA_BF16(acc[mt][nt], Al[mt], bh[sub], bh[sub + 2]);
                    }
                }
            }
        }
        __syncthreads();
    }

    const int rl = wm * 32 + (lane >> 2);
    const int cl = wn * 32 + (lane & 3) * 2;
#pragma unroll
    for (int mt = 0; mt < 2; mt++) {
#pragma unroll
        for (int nt = 0; nt < 4; nt++) {
            const int r = rl + mt * 16;
            const int c = cl + nt * 8;
            sT[(c    ) * 132 + r    ] = acc[mt][nt][0];
            sT[(c + 1) * 132 + r    ] = acc[mt][nt][1];
            sT[(c    ) * 132 + r + 8] = acc[mt][nt][2];
            sT[(c + 1) * 132 + r + 8] = acc[mt][nt][3];
        }
    }
    __syncthreads();

    for (int i = t; i < 8192; i += 256) {
        const int c = i >> 7, r = i & 127;
        const int pf = row0 + r;
        const int b  = pf / SP;
        const int p  = pf - b * SP;
        out[((size_t)b * CDIM + c0 + c) * SP + p] = sT[c * 132 + r] + sBias[c];
    }
}

// ---------------------------------------------------------------------------
extern "C" void kernel_launch(void* const* d_in, const int* in_sizes, int n_in,
                              void* d_out, int out_size)
{
    const float* x    = (const float*)d_in[0];
    const float* Wk   = (const float*)d_in[2];
    const float* Wv   = (const float*)d_in[3];
    const float* Wq   = (const float*)d_in[4];
    const float* Wout = (const float*)d_in[5];
    const float* bout = (const float*)d_in[6];
    float* out = (float*)d_out;

    cudaFuncSetAttribute(proj_mma_kernel, cudaFuncAttributeMaxDynamicSharedMemorySize,
                         PJ_SMEM);
    cudaFuncSetAttribute(attn_kernel, cudaFuncAttributeMaxDynamicSharedMemorySize,
                         ATTN_SMEM_BYTES);
    cudaFuncSetAttribute(outproj_mma_kernel, cudaFuncAttributeMaxDynamicSharedMemorySize,
                         OP_SMEM);

    convertX_kernel<<<dim3(SP / 64, CDIM / 64, BATCH), 256>>>(x);
    convertW_kernel<<<256, 256>>>(Wk, Wv, Wq, Wout);
    proj_mma_kernel<<<dim3(NPOS / 128, CDIM / 64), 256, PJ_SMEM>>>();
    attn_kernel<<<dim3(NWIN, 2), 128, ATTN_SMEM_BYTES>>>();
    outproj_mma_kernel<<<dim3(NPOS / 128, CDIM / 64), 256, OP_SMEM>>>(bout, out);
}

// round 15
// speedup vs baseline: 1.0217x; 1.0217x over previous
#include <cuda_runtime.h>
#include <cuda_bf16.h>
#include <stdint.h>

#define BATCH 4
#define CDIM  256
#define HH    120
#define WWID  120
#define SP    (HH*WWID)
#define NB    24
#define NWIN  (BATCH*NB*NB)       // 2304
#define NPOS  (BATCH*SP)          // 57600
#define QSCALE 0.17677669529663688f

#define NEGW  (-0.5f)
#define POSW  (4.0f/3.0f)
#define NORW  (-0.375f)
#define CNORW (4.0f)
#define PW    (1.8333333333333333f)   // POSW - NEGW
#define C0W   (4.375f)                // CNORW - NORW

// fp32 projections (read by attn)
__device__ float g_xk[NPOS*CDIM];
__device__ float g_xv[NPOS*CDIM];
__device__ float g_xq[NPOS*CDIM];
// bf16 split inputs for MMA
__device__ __nv_bfloat16 g_xh[NPOS*CDIM];
__device__ __nv_bfloat16 g_xl[NPOS*CDIM];
__device__ __nv_bfloat16 g_yh[NPOS*CDIM];
__device__ __nv_bfloat16 g_yl[NPOS*CDIM];
__device__ __nv_bfloat16 g_wh[4*CDIM*CDIM];   // Wk,Wv,Wq,Wout
__device__ __nv_bfloat16 g_wl[4*CDIM*CDIM];

__device__ __forceinline__ uint32_t sptr(const void* p) {
    return (uint32_t)__cvta_generic_to_shared(p);
}

#define LDM_X4(R, A) asm volatile( \
    "ldmatrix.sync.aligned.m8n8.x4.shared.b16 {%0,%1,%2,%3}, [%4];" \
    : "=r"((R)[0]), "=r"((R)[1]), "=r"((R)[2]), "=r"((R)[3]) : "r"(A))

#define MMA_BF16(D, A, B0, B1) asm volatile( \
    "mma.sync.aligned.m16n8k16.row.col.f32.bf16.bf16.f32 " \
    "{%0,%1,%2,%3},{%4,%5,%6,%7},{%8,%9},{%0,%1,%2,%3};" \
    : "+f"((D)[0]), "+f"((D)[1]), "+f"((D)[2]), "+f"((D)[3]) \
    : "r"((A)[0]), "r"((A)[1]), "r"((A)[2]), "r"((A)[3]), "r"(B0), "r"(B1))

#define CP_ASYNC16(dst, src) asm volatile( \
    "cp.async.cg.shared.global [%0], [%1], 16;" :: "r"(dst), "l"(src))
#define CP_COMMIT() asm volatile("cp.async.commit_group;")
#define CP_WAIT1()  asm volatile("cp.async.wait_group 1;")
#define CP_WAIT0()  asm volatile("cp.async.wait_group 0;")

// ---- packed f32x2 (Blackwell sm_100+) ----
#define FMA2(d, a, b) asm("fma.rn.f32x2 %0, %1, %2, %0;" : "+l"(d) : "l"(a), "l"(b))
#define ADD2(d, a, b) asm("add.rn.f32x2 %0, %1, %2;" : "=l"(d) : "l"(a), "l"(b))
#define PACK2(d, s)   asm("mov.b64 %0, {%1, %1};" : "=l"(d) : "r"(s))
#define UNPACK2(lo, hi, v) asm("mov.b64 {%0, %1}, %2;" : "=r"(lo), "=r"(hi) : "l"(v))

// ---------------------------------------------------------------------------
// Fused convert: x [b][k][p] fp32 -> g_xh/g_xl [b*SP+p][k] bf16 hi/lo
// (transpose), plus the first 256 flattened blocks also convert the 4 weight
// matrices (independent work, no ordering needed).
// ---------------------------------------------------------------------------
__global__ __launch_bounds__(256) void convert_kernel(
    const float* __restrict__ x,
    const float* __restrict__ Wk, const float* __restrict__ Wv,
    const float* __restrict__ Wq, const float* __restrict__ Wout)
{
    __shared__ float st[64][65];
    const int p0 = blockIdx.x * 64;
    const int k0 = blockIdx.y * 64;
    const int b  = blockIdx.z;
    const int t  = threadIdx.x;

    for (int idx = t; idx < 4096; idx += 256) {
        const int k = idx >> 6, p = idx & 63;
        st[k][p] = x[((size_t)b * CDIM + k0 + k) * SP + p0 + p];
    }
    __syncthreads();
    for (int idx = t; idx < 2048; idx += 256) {
        const int p = idx >> 5, kk = idx & 31, k = kk * 2;
        const float v0 = st[k][p], v1 = st[k + 1][p];
        const __nv_bfloat16 h0 = __float2bfloat16(v0);
        const __nv_bfloat16 h1 = __float2bfloat16(v1);
        const __nv_bfloat16 l0 = __float2bfloat16(v0 - __bfloat162float(h0));
        const __nv_bfloat16 l1 = __float2bfloat16(v1 - __bfloat162float(h1));
        const size_t o = ((size_t)b * SP + p0 + p) * CDIM + k0 + k;
        *(__nv_bfloat162*)&g_xh[o] = __halves2bfloat162(h0, h1);
        *(__nv_bfloat162*)&g_xl[o] = __halves2bfloat162(l0, l1);
    }

    // fold in weight conversion on the first 256 flattened blocks
    const int flat = (blockIdx.z * gridDim.y + blockIdx.y) * gridDim.x + blockIdx.x;
    if (flat < 256) {
        const int i = flat * 256 + t;      // 0..65535
        const float* srcs[4] = {Wk, Wv, Wq, Wout};
#pragma unroll
        for (int mtx = 0; mtx < 4; mtx++) {
            const float v = srcs[mtx][i];
            const __nv_bfloat16 h = __float2bfloat16(v);
            g_wh[mtx * 65536 + i] = h;
            g_wl[mtx * 65536 + i] = __float2bfloat16(v - __bfloat162float(h));
        }
    }
}

// ---------------------------------------------------------------------------
// proj3 via mma.sync, cp.async double-buffered.  KC=32, 8 chunks.
// ---------------------------------------------------------------------------
#define PJ_STAGE 51200
#define PJ_SMEM  (2*PJ_STAGE)      // 102400

__device__ __forceinline__ void pj_load_chunk(char* base, int t, int row0, int c0,
                                              int chunk)
{
    const int kc = chunk * 32;
    for (int i = t; i < 1024; i += 256) {
        const int half = i >> 9, r = (i >> 2) & 127, seg = i & 3;
        const __nv_bfloat16* src = (half ? g_xl : g_xh)
            + (size_t)(row0 + r) * CDIM + kc + seg * 8;
        CP_ASYNC16(sptr(base + half * 10240 + r * 80 + seg * 16), src);
    }
    for (int i = t; i < 1536; i += 256) {
        const int half = (i >= 768), rem = i - half * 768;
        const int pr = rem >> 8, rr = (rem >> 2) & 63, seg = rem & 3;
        const __nv_bfloat16* src = (half ? g_wl : g_wh)
            + (size_t)pr * 65536 + (size_t)(c0 + rr) * CDIM + kc + seg * 8;
        CP_ASYNC16(sptr(base + 20480 + half * 15360 + pr * 5120 + rr * 80 + seg * 16),
                   src);
    }
}

__global__ __launch_bounds__(256, 2) void proj_mma_kernel()
{
    extern __shared__ char smem[];
    const int t = threadIdx.x;
    const int warp = t >> 5, lane = t & 31;
    const int wm = warp >> 1, wn = warp & 1;
    const int row0 = blockIdx.x * 128;
    const int c0   = blockIdx.y * 64;

    float acc[3][2][4][4];
#pragma unroll
    for (int a = 0; a < 3; a++)
#pragma unroll
        for (int b = 0; b < 2; b++)
#pragma unroll
            for (int c = 0; c < 4; c++)
#pragma unroll
                for (int d = 0; d < 4; d++) acc[a][b][c][d] = 0.f;

    pj_load_chunk(smem, t, row0, c0, 0);
    CP_COMMIT();

    for (int ch = 0; ch < 8; ch++) {
        if (ch < 7) {
            pj_load_chunk(smem + ((ch + 1) & 1) * PJ_STAGE, t, row0, c0, ch + 1);
            CP_COMMIT();
            CP_WAIT1();
        } else {
            CP_WAIT0();
        }
        __syncthreads();
        char* base = smem + (ch & 1) * PJ_STAGE;

#pragma unroll
        for (int ks = 0; ks < 2; ks++) {
            uint32_t Ah[2][4], Al[2][4];
            const int colb = ks * 32 + ((lane >> 4) << 4);
#pragma unroll
            for (int mt = 0; mt < 2; mt++) {
                const int r = wm * 32 + mt * 16 + (lane & 15);
                LDM_X4(Ah[mt], sptr(base + r * 80 + colb));
                LDM_X4(Al[mt], sptr(base + 10240 + r * 80 + colb));
            }
#pragma unroll
            for (int pr = 0; pr < 3; pr++) {
#pragma unroll
                for (int pair = 0; pair < 2; pair++) {
                    const int nr = wn * 32 + pair * 16 + (lane & 15);
                    uint32_t bh[4], bl[4];
                    LDM_X4(bh, sptr(base + 20480 + pr * 5120 + nr * 80 + colb));
                    LDM_X4(bl, sptr(base + 35840 + pr * 5120 + nr * 80 + colb));
#pragma unroll
                    for (int mt = 0; mt < 2; mt++) {
#pragma unroll
                        for (int sub = 0; sub < 2; sub++) {
                            const int nt = pair * 2 + sub;
                            MMA_BF16(acc[pr][mt][nt], Ah[mt], bh[sub], bh[sub + 2]);
                            MMA_BF16(acc[pr][mt][nt], Ah[mt], bl[sub], bl[sub + 2]);
                            MMA_BF16(acc[pr][mt][nt], Al[mt], bh[sub], bh[sub + 2]);
                        }
                    }
                }
            }
        }
        __syncthreads();
    }

    const int rbase = row0 + wm * 32 + (lane >> 2);
    const int cbase = c0 + wn * 32 + (lane & 3) * 2;
    float* dsts[3] = {g_xk, g_xv, g_xq};
#pragma unroll
    for (int pr = 0; pr < 3; pr++) {
        const float s = (pr == 2) ? QSCALE : 1.f;
#pragma unroll
        for (int mt = 0; mt < 2; mt++) {
#pragma unroll
            for (int nt = 0; nt < 4; nt++) {
                const int r = rbase + mt * 16;
                const int c = cbase + nt * 8;
                float* d = dsts[pr];
                *(float2*)&d[(size_t)r * CDIM + c] =
                    make_float2(acc[pr][mt][nt][0] * s, acc[pr][mt][nt][1] * s);
                *(float2*)&d[(size_t)(r + 8) * CDIM + c] =
                    make_float2(acc[pr][mt][nt][2] * s, acc[pr][mt][nt][3] * s);
            }
        }
    }
}

// ---------------------------------------------------------------------------
// attn: CTA = (window, head-half). 128 threads = 4 warps = 4 heads, lane = q.
// Phase 1: S[p] streamed to smem at strip_base + p*32 + lane — i.e. INTO row p
// of this warp's own (just-read) K strip.  Row p is fully consumed by the
// converged warp before the store instruction issues, and warp h touches only
// strip h -> race-free.  Store/load bank = lane -> conflict-free.
// Phase 2: rolling 3-column window reads S as Ss[i*32]; fused AV over sV.
// (R12 configuration: best measured attn = 244.3us.)
// ---------------------------------------------------------------------------
#define ATTN_SMEM_BYTES (2 * 4 * 49 * 32 * 4)   // 50176
__global__ __launch_bounds__(128, 4) void attn_kernel()
{
    extern __shared__ float sm_att[];
    float* sK = sm_att;                // 6272 floats; overwritten row-by-row by S
    float* sV = sm_att + 4 * 49 * 32;

    const int blk  = blockIdx.x;
    const int half = blockIdx.y;
    const int b    = blk / (NB * NB);
    const int wrem = blk % (NB * NB);
    const int wy = wrem / NB, wx = wrem % NB;
    const int t = threadIdx.x;
    const int c0 = half * 128;

    const int ky0 = wy * 5 - 1, kx0 = wx * 5 - 1;
    for (int idx = t; idx < 49 * 32; idx += 128) {
        const int r  = idx >> 5;
        const int c4 = idx & 31;
        const int y  = ky0 + r / 7;
        const int xx = kx0 + r % 7;
        float4 vk = make_float4(0.f, 0.f, 0.f, 0.f);
        float4 vv = make_float4(0.f, 0.f, 0.f, 0.f);
        if (y >= 0 && y < HH && xx >= 0 && xx < WWID) {
            const size_t g = ((size_t)b * SP + y * WWID + xx) * CDIM + c0 + c4 * 4;
            vk = *(const float4*)&g_xk[g];
            vv = *(const float4*)&g_xv[g];
        }
        const int f = c4 * 4, hl = f >> 5, cc = f & 31;
        *(float4*)&sK[(hl * 49 + r) * 32 + cc] = vk;
        *(float4*)&sV[(hl * 49 + r) * 32 + cc] = vv;
    }
    __syncthreads();

    const int lane = t & 31;
    const int hl   = t >> 5;          // warp = head within this half
    if (lane < 25) {
        const int q = lane;
        const int qy = q / 5, qx = q % 5;
        const size_t qpos = ((size_t)b * SP + (wy * 5 + qy) * WWID + wx * 5 + qx) * CDIM
                            + (half * 4 + hl) * 32;
        // lane's S storage: strip_base + p*32 + lane  (inside row p, bank=lane)
        float* Ss = &sK[hl * 49 * 32 + lane];

        float m;
        {
            // Q as 16 packed f32x2
            unsigned long long qp[16];
#pragma unroll
            for (int j = 0; j < 8; j++) {
                const ulonglong2 v = *(const ulonglong2*)&g_xq[qpos + j * 4];
                qp[2*j] = v.x; qp[2*j+1] = v.y;
            }

            // S[p] = Q . K_p, stored into row p right after the warp reads it.
            float mpos = -3.4e38f, mneg = 3.4e38f;
#pragma unroll
            for (int p = 0; p < 49; p++) {
                const float* kr = &sK[(hl * 49 + p) * 32];
                unsigned long long a0 = 0ull, a1 = 0ull;
#pragma unroll
                for (int j = 0; j < 8; j++) {
                    const ulonglong2 kv = *(const ulonglong2*)&kr[j * 4];
                    FMA2(a0, qp[2*j],   kv.x);
                    FMA2(a1, qp[2*j+1], kv.y);
                }
                unsigned long long asum; ADD2(asum, a0, a1);
                uint32_t lo, hi; UNPACK2(lo, hi, asum);
                const float sv = __uint_as_float(lo) + __uint_as_float(hi);
                mpos = fmaxf(mpos, sv);
                mneg = fminf(mneg, sv);
                Ss[p * 32] = sv;
            }
            m = 4.0f * mpos - 3.0f * mneg;
        }

        // phase 2: streaming 3-row A window + fused AV
        unsigned long long o2[16];
#pragma unroll
        for (int j = 0; j < 16; j++) o2[j] = 0ull;
        float A0[7], A1[7], A2[7];
#pragma unroll
        for (int j = 0; j < 7; j++) { A0[j] = 0.f; A1[j] = 0.f; A2[j] = 0.f; }

        float ssum = 0.f;
#pragma unroll
        for (int ky = 0; ky < 5; ky++) {
            // rolling 3x3 column window over S rows ky..ky+2
            float a0 = Ss[(ky*7)*32],       a1 = Ss[((ky+1)*7)*32],       a2 = Ss[((ky+2)*7)*32];
            float b0 = Ss[(ky*7 + 1)*32],   b1 = Ss[((ky+1)*7 + 1)*32],   b2 = Ss[((ky+2)*7 + 1)*32];
#pragma unroll
            for (int kx = 0; kx < 5; kx++) {
                const float t0 = Ss[(ky*7 + kx + 2)*32];
                const float t1 = Ss[((ky+1)*7 + kx + 2)*32];
                const float t2 = Ss[((ky+2)*7 + kx + 2)*32];
                const float tl = a0, l = a1, bl = a2;
                const float u  = b0, c = b1, d  = b2;
                const float tr = t0, r = t1, br = t2;
                const float s_ud = u + d, s_lr = l + r;
                const float dg = tl + br, ad = tr + bl;
                const float sum9 = ((s_ud + s_lr) + (dg + ad)) + c;
                const float base = fmaf(NEGW, sum9, -m);
                const float e0 = __expf(fmaf(NORW, sum9, fmaf(C0W, c, -m)));
                const float e1 = __expf(fmaf(PW, s_ud + c, base));
                const float e2 = __expf(fmaf(PW, s_lr + c, base));
                const float e3 = __expf(fmaf(PW, dg + c, base));
                const float e4 = __expf(fmaf(PW, ad + c, base));
                const float e5 = __expf(fmaf(PW, (u + l) + c, base));
                const float e6 = __expf(fmaf(PW, (u + r) + c, base));
                const float e7 = __expf(fmaf(PW, (l + d) + c, base));
                const float e8 = __expf(fmaf(PW, (r + d) + c, base));
                const float E = ((e1 + e2) + (e3 + e4)) + ((e5 + e6) + (e7 + e8));
                ssum += E + e0;
                const float basea = fmaf(NEGW, E, NORW * e0);
                A0[kx  ] += fmaf(PW, e3, basea);
                A0[kx+1] += fmaf(PW, (e1 + e5) + e6, basea);
                A0[kx+2] += fmaf(PW, e4, basea);
                A1[kx  ] += fmaf(PW, (e2 + e5) + e7, basea);
                A1[kx+1] += fmaf(PW, E, fmaf(C0W, e0, basea));
                A1[kx+2] += fmaf(PW, (e2 + e6) + e8, basea);
                A2[kx  ] += fmaf(PW, e4, basea);
                A2[kx+1] += fmaf(PW, (e1 + e7) + e8, basea);
                A2[kx+2] += fmaf(PW, e3, basea);
                a0 = b0; a1 = b1; a2 = b2;
                b0 = t0; b1 = t1; b2 = t2;
            }
            // row ky is final: fused AV (V loads broadcast warp-wide)
#pragma unroll
            for (int px = 0; px < 7; px++) {
                unsigned long long aa; PACK2(aa, __float_as_uint(A0[px]));
                const float* vr = &sV[(hl * 49 + ky * 7 + px) * 32];
#pragma unroll
                for (int j = 0; j < 8; j++) {
                    const ulonglong2 vv = *(const ulonglong2*)&vr[j * 4];
                    FMA2(o2[2*j],   aa, vv.x);
                    FMA2(o2[2*j+1], aa, vv.y);
                }
            }
#pragma unroll
            for (int j = 0; j < 7; j++) { A0[j] = A1[j]; A1[j] = A2[j]; A2[j] = 0.f; }
        }
        // rows 5 (A0) and 6 (A1)
#pragma unroll
        for (int rr = 0; rr < 2; rr++) {
#pragma unroll
            for (int px = 0; px < 7; px++) {
                const float a = rr ? A1[px] : A0[px];
                unsigned long long aa; PACK2(aa, __float_as_uint(a));
                const float* vr = &sV[(hl * 49 + (5 + rr) * 7 + px) * 32];
#pragma unroll
                for (int j = 0; j < 8; j++) {
                    const ulonglong2 vv = *(const ulonglong2*)&vr[j * 4];
                    FMA2(o2[2*j],   aa, vv.x);
                    FMA2(o2[2*j+1], aa, vv.y);
                }
            }
        }

        const float inv = 1.0f / ssum;
        uint32_t hw[16], lw[16];
#pragma unroll
        for (int j = 0; j < 16; j++) {
            uint32_t lo, hi; UNPACK2(lo, hi, o2[j]);
            const float v0 = __uint_as_float(lo) * inv;
            const float v1 = __uint_as_float(hi) * inv;
            const __nv_bfloat16 h0 = __float2bfloat16(v0);
            const __nv_bfloat16 h1 = __float2bfloat16(v1);
            const __nv_bfloat16 l0 = __float2bfloat16(v0 - __bfloat162float(h0));
            const __nv_bfloat16 l1 = __float2bfloat16(v1 - __bfloat162float(h1));
            __nv_bfloat162 hp = __halves2bfloat162(h0, h1);
            __nv_bfloat162 lp = __halves2bfloat162(l0, l1);
            hw[j] = *(uint32_t*)&hp;
            lw[j] = *(uint32_t*)&lp;
        }
#pragma unroll
        for (int j = 0; j < 4; j++) {
            *(uint4*)&g_yh[qpos + j * 8] = make_uint4(hw[4*j], hw[4*j+1], hw[4*j+2], hw[4*j+3]);
            *(uint4*)&g_yl[qpos + j * 8] = make_uint4(lw[4*j], lw[4*j+1], lw[4*j+2], lw[4*j+3]);
        }
    }
}

// ---------------------------------------------------------------------------
// outproj via mma.sync, cp.async double-buffered.  KC=32, 8 chunks.
// ---------------------------------------------------------------------------
#define OP_STAGE 30720
#define OP_BIAS  (2*OP_STAGE)              // 61440, 256B bias
#define OP_SMEM  (2*OP_STAGE + 256)

__device__ __forceinline__ void op_load_chunk(char* base, int t, int row0, int c0,
                                              int chunk)
{
    const int kc = chunk * 32;
    for (int i = t; i < 1024; i += 256) {
        const int half = i >> 9, r = (i >> 2) & 127, seg = i & 3;
        const __nv_bfloat16* src = (half ? g_yl : g_yh)
            + (size_t)(row0 + r) * CDIM + kc + seg * 8;
        CP_ASYNC16(sptr(base + half * 10240 + r * 80 + seg * 16), src);
    }
    for (int i = t; i < 512; i += 256) {
        const int half = i >> 8, rr = (i >> 2) & 63, seg = i & 3;
        const __nv_bfloat16* src = (half ? g_wl : g_wh)
            + (size_t)3 * 65536 + (size_t)(c0 + rr) * CDIM + kc + seg * 8;
        CP_ASYNC16(sptr(base + 20480 + half * 5120 + rr * 80 + seg * 16), src);
    }
}

__global__ __launch_bounds__(256, 2) void outproj_mma_kernel(
    const float* __restrict__ bout, float* __restrict__ out)
{
    extern __shared__ char smem[];
    float* sT = (float*)smem;
    float* sBias = (float*)(smem + OP_BIAS);
    const int t = threadIdx.x;
    const int warp = t >> 5, lane = t & 31;
    const int wm = warp >> 1, wn = warp & 1;
    const int row0 = blockIdx.x * 128;
    const int c0   = blockIdx.y * 64;

    if (t < 64) sBias[t] = bout[c0 + t];

    float acc[2][4][4];
#pragma unroll
    for (int b = 0; b < 2; b++)
#pragma unroll
        for (int c = 0; c < 4; c++)
#pragma unroll
            for (int d = 0; d < 4; d++) acc[b][c][d] = 0.f;

    op_load_chunk(smem, t, row0, c0, 0);
    CP_COMMIT();

    for (int ch = 0; ch < 8; ch++) {
        if (ch < 7) {
            op_load_chunk(smem + ((ch + 1) & 1) * OP_STAGE, t, row0, c0, ch + 1);
            CP_COMMIT();
            CP_WAIT1();
        } else {
            CP_WAIT0();
        }
        __syncthreads();
        char* base = smem + (ch & 1) * OP_STAGE;

#pragma unroll
        for (int ks = 0; ks < 2; ks++) {
            uint32_t Ah[2][4], Al[2][4];
            const int colb = ks * 32 + ((lane >> 4) << 4);
#pragma unroll
            for (int mt = 0; mt < 2; mt++) {
                const int r = wm * 32 + mt * 16 + (lane & 15);
                LDM_X4(Ah[mt], sptr(base + r * 80 + colb));
                LDM_X4(Al[mt], sptr(base + 10240 + r * 80 + colb));
            }
#pragma unroll
            for (int pair = 0; pair < 2; pair++) {
                const int nr = wn * 32 + pair * 16 + (lane & 15);
                uint32_t bh[4], bl[4];
                LDM_X4(bh, sptr(base + 20480 + nr * 80 + colb));
                LDM_X4(bl, sptr(base + 25600 + nr * 80 + colb));
#pragma unroll
                for (int mt = 0; mt < 2; mt++) {
#pragma unroll
                    for (int sub = 0; sub < 2; sub++) {
                        const int nt = pair * 2 + sub;
                        MMA_BF16(acc[mt][nt], Ah[mt], bh[sub], bh[sub + 2]);
                        MMA_BF16(acc[mt][nt], Ah[mt], bl[sub], bl[sub + 2]);
                        MMA_BF16(acc[mt][nt], Al[mt], bh[sub], bh[sub + 2]);
                    }
                }
            }
        }
        __syncthreads();
    }

    const int rl = wm * 32 + (lane >> 2);
    const int cl = wn * 32 + (lane & 3) * 2;
#pragma unroll
    for (int mt = 0; mt < 2; mt++) {
#pragma unroll
        for (int nt = 0; nt < 4; nt++) {
            const int r = rl + mt * 16;
            const int c = cl + nt * 8;
            sT[(c    ) * 132 + r    ] = acc[mt][nt][0];
            sT[(c + 1) * 132 + r    ] = acc[mt][nt][1];
            sT[(c    ) * 132 + r + 8] = acc[mt][nt][2];
            sT[(c + 1) * 132 + r + 8] = acc[mt][nt][3];
        }
    }
    __syncthreads();

    for (int i = t; i < 8192; i += 256) {
        const int c = i >> 7, r = i & 127;
        const int pf = row0 + r;
        const int b  = pf / SP;
        const int p  = pf - b * SP;
        out[((size_t)b * CDIM + c0 + c) * SP + p] = sT[c * 132 + r] + sBias[c];
    }
}

// ---------------------------------------------------------------------------
extern "C" void kernel_launch(void* const* d_in, const int* in_sizes, int n_in,
                              void* d_out, int out_size)
{
    const float* x    = (const float*)d_in[0];
    const float* Wk   = (const float*)d_in[2];
    const float* Wv   = (const float*)d_in[3];
    const float* Wq   = (const float*)d_in[4];
    const float* Wout = (const float*)d_in[5];
    const float* bout = (const float*)d_in[6];
    float* out = (float*)d_out;

    cudaFuncSetAttribute(proj_mma_kernel, cudaFuncAttributeMaxDynamicSharedMemorySize,
                         PJ_SMEM);
    cudaFuncSetAttribute(attn_kernel, cudaFuncAttributeMaxDynamicSharedMemorySize,
                         ATTN_SMEM_BYTES);
    cudaFuncSetAttribute(outproj_mma_kernel, cudaFuncAttributeMaxDynamicSharedMemorySize,
                         OP_SMEM);

    convert_kernel<<<dim3(SP / 64, CDIM / 64, BATCH), 256>>>(x, Wk, Wv, Wq, Wout);
    proj_mma_kernel<<<dim3(NPOS / 128, CDIM / 64), 256, PJ_SMEM>>>();
    attn_kernel<<<dim3(NWIN, 2), 128, ATTN_SMEM_BYTES>>>();
    outproj_mma_kernel<<<dim3(NPOS / 128, CDIM / 64), 256, OP_SMEM>>>(bout, out);
}